// round 12
// baseline (speedup 1.0000x reference)
#include <cuda_runtime.h>
#include <stdint.h>

// RescaleProbMask: x (32, 256, 256, 16) fp32.
//   p[h,w] = mean over (batch, channel); out = scale(p)*x + bias(p).
//
// Narrow-barrier variant of the 43.5us best: 128-thread CTAs (4 warps,
// 4 pixels/CTA, 16 CTAs/SM). Halves the __syncthreads span (4 warps vs 8)
// and doubles the number of independently-scheduled CTAs per SM, reducing
// barrier phase-locking of memory issue while preserving all the known-good
// invariants: 64B payload/thread, 4-line wavefronts per warp load, regs<=32,
// 2048 threads/SM, write-through stores (R10 win).
//
// Mapping: warp w covers batches 8w..8w+7. Load k (k=0..3): lanes 0-15 read
// batch 8w+2k, lanes 16-31 read batch 8w+2k+1; each half-warp covers the
// tile's 256B segment (4 pixels x 16 ch) for that batch.
// Lane's 16 floats = channels [(li&3)*4,+4) of pixel li>>2 over 4 batches.
// Reduce: lane sum -> shfl_xor(1),(2) (16 channels) -> shfl_xor(16) (batch
// pairs) -> 4x4 smem -> 128-thread barrier -> (scale,bias) -> FMA -> st.wt.

#define NB    32
#define NHW   (256 * 256)
#define NC    16
#define ALPHA 0.25f

#define PIX_PER_CTA 4
#define TILE_F      (PIX_PER_CTA * NC)       // 64 floats per batch per tile
#define PLANE       ((size_t)NHW * NC)       // 1048576 floats per batch plane

__device__ __forceinline__ float4 ld_x16(const float* p) {
    float4 v;
    asm("ld.global.nc.L1::no_allocate.v4.f32 {%0,%1,%2,%3}, [%4];"
        : "=f"(v.x), "=f"(v.y), "=f"(v.z), "=f"(v.w) : "l"(p));
    return v;
}

__device__ __forceinline__ void st_out16_wt(float* p, float4 v) {
    asm volatile("st.global.wt.v4.f32 [%0], {%1,%2,%3,%4};"
                 :: "l"(p), "f"(v.x), "f"(v.y), "f"(v.z), "f"(v.w)
                 : "memory");
}

__global__ __launch_bounds__(128, 16)
void rescale_prob_mask_kernel(const float* __restrict__ x,
                              float* __restrict__ out) {
    __shared__ float psum[PIX_PER_CTA][4];   // [pixel][warp]

    const int tid  = threadIdx.x;
    const int warp = tid >> 5;               // 0..3
    const int lane = tid & 31;
    const int li   = lane & 15;              // slot within half-warp
    const int half = lane >> 4;              // batch parity within pair
    const int pix  = li >> 2;                // pixel within CTA (0..3)

    // element offset of this lane's float4 within a batch plane
    const size_t off = (size_t)blockIdx.x * TILE_F + (size_t)li * 4;

    const int bb = warp * 8 + half;          // base batch for this lane

    const size_t i0 = (size_t)(bb + 0) * PLANE + off;
    const size_t i1 = (size_t)(bb + 2) * PLANE + off;
    const size_t i2 = (size_t)(bb + 4) * PLANE + off;
    const size_t i3 = (size_t)(bb + 6) * PLANE + off;

    float4 v0 = ld_x16(x + i0);
    float4 v1 = ld_x16(x + i1);
    float4 v2 = ld_x16(x + i2);
    float4 v3 = ld_x16(x + i3);

    // lane-local partial sum (4 batches x 4 channels of pixel `pix`)
    float s = ((v0.x + v0.y) + (v0.z + v0.w))
            + ((v1.x + v1.y) + (v1.z + v1.w))
            + ((v2.x + v2.y) + (v2.z + v2.w))
            + ((v3.x + v3.y) + (v3.z + v3.w));

    // xor1,2: the other 12 channels of the pixel; xor16: other batch parity
    s += __shfl_xor_sync(0xffffffffu, s, 1);
    s += __shfl_xor_sync(0xffffffffu, s, 2);
    s += __shfl_xor_sync(0xffffffffu, s, 16);

    if (lane < 16 && (li & 3) == 0)
        psum[pix][warp] = s;                 // s = warp's 8 batches, 16 ch
    __syncthreads();                          // 128-thread barrier only

    const float tot = psum[pix][0] + psum[pix][1]
                    + psum[pix][2] + psum[pix][3];

    const float p = tot * (1.0f / (NB * NC));

    float scale, bias;
    if (p >= ALPHA) {
        scale = ALPHA / p;
        bias  = 0.0f;
    } else {
        const float beta = (1.0f - ALPHA) / (1.0f - p);
        scale = beta;
        bias  = 1.0f - beta;
    }

    v0.x = fmaf(scale, v0.x, bias); v0.y = fmaf(scale, v0.y, bias);
    v0.z = fmaf(scale, v0.z, bias); v0.w = fmaf(scale, v0.w, bias);
    v1.x = fmaf(scale, v1.x, bias); v1.y = fmaf(scale, v1.y, bias);
    v1.z = fmaf(scale, v1.z, bias); v1.w = fmaf(scale, v1.w, bias);
    v2.x = fmaf(scale, v2.x, bias); v2.y = fmaf(scale, v2.y, bias);
    v2.z = fmaf(scale, v2.z, bias); v2.w = fmaf(scale, v2.w, bias);
    v3.x = fmaf(scale, v3.x, bias); v3.y = fmaf(scale, v3.y, bias);
    v3.z = fmaf(scale, v3.z, bias); v3.w = fmaf(scale, v3.w, bias);

    st_out16_wt(out + i0, v0);
    st_out16_wt(out + i1, v1);
    st_out16_wt(out + i2, v2);
    st_out16_wt(out + i3, v3);
}

extern "C" void kernel_launch(void* const* d_in, const int* in_sizes, int n_in,
                              void* d_out, int out_size) {
    const float* x   = (const float*)d_in[0];
    float*       out = (float*)d_out;

    const int blocks = NHW / PIX_PER_CTA;   // 16384
    rescale_prob_mask_kernel<<<blocks, 128>>>(x, out);
}

// round 13
// speedup vs baseline: 1.0382x; 1.0382x over previous
#include <cuda_runtime.h>
#include <stdint.h>

// RescaleProbMask: x (32, 256, 256, 16) fp32.
//   p[h,w] = mean over (batch, channel); out = scale(p)*x + bias(p).
//
// Clean isolate of barrier width: R11's 128-thread/4-pixel CTA shape with
// EXACTLY R10's memory ops (the 43.5us best):
//   ld.global.nc.L2::evict_last.v4.b64  (256-bit x loads)
//   st.global.wt.v4.b64                 (256-bit write-through stores)
// 16 CTAs/SM, 64B payload/thread, regs<=32, barrier spans 4 warps.
//
// Mapping: warp w covers batches 8w..8w+7. One 1KB warp load = 4 batches
// (lanes grouped 8/batch, each lane 32B of the tile's 256B segment).
// Lane (q=lane>>3, li8=lane&7) reads batch 8w+q (+4 on 2nd load), pixel
// li8>>1, channel half li8&1.
// Reduce: xor1 (channel halves) + xor8 + xor16 (batch quarters) ->
// psum[4][4] smem -> 128-thread barrier -> (scale,bias) -> FMA -> st.wt.

#define NB    32
#define NHW   (256 * 256)
#define NC    16
#define ALPHA 0.25f

#define PIX_PER_CTA 4
#define TILE_F      (PIX_PER_CTA * NC)       // 64 floats = 256B per batch/tile
#define PLANE       ((size_t)NHW * NC)       // 1048576 floats per batch plane

__device__ __forceinline__ void ld_x32(const float* p, float* v) {
    uint64_t q0, q1, q2, q3;
    asm("ld.global.nc.L2::evict_last.v4.b64 {%0,%1,%2,%3}, [%4];"
        : "=l"(q0), "=l"(q1), "=l"(q2), "=l"(q3) : "l"(p));
    asm("mov.b64 {%0,%1}, %2;" : "=f"(v[0]), "=f"(v[1]) : "l"(q0));
    asm("mov.b64 {%0,%1}, %2;" : "=f"(v[2]), "=f"(v[3]) : "l"(q1));
    asm("mov.b64 {%0,%1}, %2;" : "=f"(v[4]), "=f"(v[5]) : "l"(q2));
    asm("mov.b64 {%0,%1}, %2;" : "=f"(v[6]), "=f"(v[7]) : "l"(q3));
}

__device__ __forceinline__ void st_out32_wt(float* p, const float* v) {
    uint64_t q0, q1, q2, q3;
    asm("mov.b64 %0, {%1,%2};" : "=l"(q0) : "f"(v[0]), "f"(v[1]));
    asm("mov.b64 %0, {%1,%2};" : "=l"(q1) : "f"(v[2]), "f"(v[3]));
    asm("mov.b64 %0, {%1,%2};" : "=l"(q2) : "f"(v[4]), "f"(v[5]));
    asm("mov.b64 %0, {%1,%2};" : "=l"(q3) : "f"(v[6]), "f"(v[7]));
    asm volatile("st.global.wt.v4.b64 [%0], {%1,%2,%3,%4};"
                 :: "l"(p), "l"(q0), "l"(q1), "l"(q2), "l"(q3) : "memory");
}

__global__ __launch_bounds__(128, 16)
void rescale_prob_mask_kernel(const float* __restrict__ x,
                              float* __restrict__ out) {
    __shared__ float psum[PIX_PER_CTA][4];   // [pixel][warp]

    const int tid  = threadIdx.x;
    const int warp = tid >> 5;               // 0..3
    const int lane = tid & 31;
    const int li8  = lane & 7;               // slot within batch segment
    const int q    = lane >> 3;              // batch quarter (0..3)
    const int pix  = li8 >> 1;               // pixel within CTA (0..3)

    // element offset of this lane's 8-float chunk within a batch plane
    const size_t off = (size_t)blockIdx.x * TILE_F + (size_t)li8 * 8;

    const int b0 = warp * 8 + q;             // first batch for this lane
    const int b1 = b0 + 4;                   // second batch

    const size_t i0 = (size_t)b0 * PLANE + off;
    const size_t i1 = (size_t)b1 * PLANE + off;

    float a[8], b[8];
    ld_x32(x + i0, a);
    ld_x32(x + i1, b);

    // lane-local partial sum (2 batches x 8 channels of pixel `pix`)
    float s = ((a[0] + a[1]) + (a[2] + a[3])) + ((a[4] + a[5]) + (a[6] + a[7]))
            + ((b[0] + b[1]) + (b[2] + b[3])) + ((b[4] + b[5]) + (b[6] + b[7]));

    // xor1: other channel half; xor8/xor16: other batch quarters
    s += __shfl_xor_sync(0xffffffffu, s, 1);
    s += __shfl_xor_sync(0xffffffffu, s, 8);
    s += __shfl_xor_sync(0xffffffffu, s, 16);

    if (lane < 8 && (lane & 1) == 0)
        psum[pix][warp] = s;                 // warp's 8 batches, all 16 ch
    __syncthreads();                          // spans only 4 warps

    const float tot = psum[pix][0] + psum[pix][1]
                    + psum[pix][2] + psum[pix][3];

    const float p = tot * (1.0f / (NB * NC));

    float scale, bias;
    if (p >= ALPHA) {
        scale = ALPHA / p;
        bias  = 0.0f;
    } else {
        const float beta = (1.0f - ALPHA) / (1.0f - p);
        scale = beta;
        bias  = 1.0f - beta;
    }

    #pragma unroll
    for (int k = 0; k < 8; k++) {
        a[k] = fmaf(scale, a[k], bias);
        b[k] = fmaf(scale, b[k], bias);
    }

    st_out32_wt(out + i0, a);
    st_out32_wt(out + i1, b);
}

extern "C" void kernel_launch(void* const* d_in, const int* in_sizes, int n_in,
                              void* d_out, int out_size) {
    const float* x   = (const float*)d_in[0];
    float*       out = (float*)d_out;

    const int blocks = NHW / PIX_PER_CTA;   // 16384
    rescale_prob_mask_kernel<<<blocks, 128>>>(x, out);
}